// round 1
// baseline (speedup 1.0000x reference)
#include <cuda_runtime.h>
#include <math.h>

// ---------------------------------------------------------------------------
// Shapes:
//   x     : [64, 3, 224, 224] f32
//   w1    : [64, 3, 3, 3]   b1: [64]
//   w2    : [128, 64, 3, 3] b2: [128]
//   wf    : [128, 2]        bf: [2]
// conv: 3x3, stride 2, SAME (pad_lo = 0, pad_hi = 1 in both dims)
//   h1 = relu(conv1(x))   : [64, 64, 112, 112]
//   h2 = relu(conv2(h1))  : [64, 128, 56, 56]   (never materialized; pooled)
//   g  = mean(h2, HW)     : [64, 128]
//   logits = g @ wf + bf  : [64, 2]
// output = where(conf_t <= 0.9, 0.7*t + 0.3*f, t); freq = mean(mask)
// ---------------------------------------------------------------------------

// Scratch (device globals: allocation-free rule)
__device__ float g_h1[64u * 64u * 112u * 112u];   // 205.5 MB, reused per expert
__device__ float g_part[2][64 * 56 * 128];        // per-(b,oh) pooled partials
__device__ float g_log[64 * 4];                   // tl0,tl1,fl0,fl1 per batch

// ---------------------------------------------------------------------------
// conv1: [B,3,224,224] -> relu -> [B,64,112,112]
// grid (112, 64) = (oh, b); 256 threads: 16 oc-groups(x4 oc) * 16 ow-groups(x7 ow)
// ---------------------------------------------------------------------------
__global__ __launch_bounds__(256) void conv1_kernel(
    const float* __restrict__ x, const float* __restrict__ w,
    const float* __restrict__ bias)
{
    int oh = blockIdx.x;
    int b  = blockIdx.y;
    __shared__ float s_in[3][3][228];   // [ic][kh][col]; cols 0..224 valid (224 = zero pad)
    __shared__ float s_w[64 * 27];
    __shared__ float s_b[64];
    int tid = threadIdx.x;

    for (int i = tid; i < 64 * 27; i += 256) s_w[i] = w[i];
    if (tid < 64) s_b[tid] = bias[tid];
    for (int i = tid; i < 3 * 3 * 225; i += 256) {
        int c  = i % 225;
        int t  = i / 225;
        int r  = t % 3;
        int ic = t / 3;
        int ih = 2 * oh + r;
        float v = 0.f;
        if (ih < 224 && c < 224)
            v = x[(((size_t)b * 3 + ic) * 224 + ih) * 224 + c];
        s_in[ic][r][c] = v;
    }
    __syncthreads();

    int owg = tid & 15;        // ow = owg + 16*p, p<7  (covers 0..111)
    int ocg = tid >> 4;
    int oc0 = ocg * 4;

    float acc[4][7];
    #pragma unroll
    for (int u = 0; u < 4; u++) {
        float bv = s_b[oc0 + u];
        #pragma unroll
        for (int p = 0; p < 7; p++) acc[u][p] = bv;
    }

    #pragma unroll
    for (int ic = 0; ic < 3; ic++) {
        #pragma unroll
        for (int r = 0; r < 3; r++) {
            float w0[4], w1[4], w2[4];
            #pragma unroll
            for (int u = 0; u < 4; u++) {
                const float* wp = &s_w[(oc0 + u) * 27 + ic * 9 + r * 3];
                w0[u] = wp[0]; w1[u] = wp[1]; w2[u] = wp[2];
            }
            #pragma unroll
            for (int p = 0; p < 7; p++) {
                int cb = 2 * (owg + 16 * p);
                float i0 = s_in[ic][r][cb];
                float i1 = s_in[ic][r][cb + 1];
                float i2 = s_in[ic][r][cb + 2];
                #pragma unroll
                for (int u = 0; u < 4; u++) acc[u][p] += w0[u] * i0;
                #pragma unroll
                for (int u = 0; u < 4; u++) acc[u][p] += w1[u] * i1;
                #pragma unroll
                for (int u = 0; u < 4; u++) acc[u][p] += w2[u] * i2;
            }
        }
    }

    #pragma unroll
    for (int u = 0; u < 4; u++) {
        float* op = &g_h1[(((size_t)b * 64 + oc0 + u) * 112 + oh) * 112];
        #pragma unroll
        for (int p = 0; p < 7; p++) {
            float v = acc[u][p];
            op[owg + 16 * p] = v > 0.f ? v : 0.f;
        }
    }
}

// ---------------------------------------------------------------------------
// conv2 + bias + relu + spatial pool (fused): h1 -> per-(b,oh) pooled partials
// grid (56, 64) = (oh, b); 256 threads: 32 oc-groups(x4 oc) * 8 ow-groups(x7 ow)
// smem: 8 ic staged per step (input rows + weights)
// ---------------------------------------------------------------------------
__global__ __launch_bounds__(256) void conv2_kernel(
    int expert, const float* __restrict__ w, const float* __restrict__ bias)
{
    int oh = blockIdx.x;
    int b  = blockIdx.y;
    __shared__ float s_in[8][3][116];   // cols 0..112 valid (112 = zero pad)
    __shared__ float s_w[8][1152];      // [icl][oc*9 + k]
    __shared__ float s_b[128];
    int tid = threadIdx.x;
    if (tid < 128) s_b[tid] = bias[tid];

    int owg = tid & 7;          // ow = owg + 8*p, p<7 (covers 0..55)
    int oc0 = (tid >> 3) * 4;   // 32 groups * 4 oc = 128

    float acc[4][7];
    #pragma unroll
    for (int u = 0; u < 4; u++)
        #pragma unroll
        for (int p = 0; p < 7; p++) acc[u][p] = 0.f;

    for (int ic0 = 0; ic0 < 64; ic0 += 8) {
        __syncthreads();
        // stage input: 8 ic * 3 rows * 113 cols
        for (int i = tid; i < 8 * 3 * 113; i += 256) {
            int cc  = i % 113;
            int t   = i / 113;
            int r   = t % 3;
            int icl = t / 3;
            int ih  = 2 * oh + r;
            float v = 0.f;
            if (ih < 112 && cc < 112)
                v = g_h1[(((size_t)b * 64 + ic0 + icl) * 112 + ih) * 112 + cc];
            s_in[icl][r][cc] = v;
        }
        // stage weights: 8 ic * 128 oc * 9
        for (int i = tid; i < 8 * 1152; i += 256) {
            int k   = i % 9;
            int t   = i / 9;
            int oc  = t & 127;
            int icl = t >> 7;
            s_w[icl][oc * 9 + k] = w[((size_t)oc * 64 + ic0 + icl) * 9 + k];
        }
        __syncthreads();

        #pragma unroll 2
        for (int icl = 0; icl < 8; icl++) {
            #pragma unroll
            for (int r = 0; r < 3; r++) {
                float w0[4], w1[4], w2[4];
                #pragma unroll
                for (int u = 0; u < 4; u++) {
                    const float* wp = &s_w[icl][(oc0 + u) * 9 + r * 3];
                    w0[u] = wp[0]; w1[u] = wp[1]; w2[u] = wp[2];
                }
                #pragma unroll
                for (int p = 0; p < 7; p++) {
                    int cb = 2 * (owg + 8 * p);
                    float i0 = s_in[icl][r][cb];
                    float i1 = s_in[icl][r][cb + 1];
                    float i2 = s_in[icl][r][cb + 2];
                    #pragma unroll
                    for (int u = 0; u < 4; u++) acc[u][p] += w0[u] * i0;
                    #pragma unroll
                    for (int u = 0; u < 4; u++) acc[u][p] += w1[u] * i1;
                    #pragma unroll
                    for (int u = 0; u < 4; u++) acc[u][p] += w2[u] * i2;
                }
            }
        }
    }

    // bias + relu + pool over this thread's 7 pixels, then over the 8 ow-groups
    #pragma unroll
    for (int u = 0; u < 4; u++) {
        float bv = s_b[oc0 + u];
        float s = 0.f;
        #pragma unroll
        for (int p = 0; p < 7; p++) {
            float v = acc[u][p] + bv;
            s += v > 0.f ? v : 0.f;
        }
        #pragma unroll
        for (int off = 4; off; off >>= 1)
            s += __shfl_down_sync(0xffffffffu, s, off);
        if (owg == 0)
            g_part[expert][((b * 56 + oh) * 128) + oc0 + u] = s;   // deterministic
    }
}

// ---------------------------------------------------------------------------
// final1: finish GAP (sum 56 oh-partials), FC -> logits per batch
// grid 64 (b); 128 threads (c)
// ---------------------------------------------------------------------------
__global__ __launch_bounds__(128) void final1_kernel(
    const float* __restrict__ twf, const float* __restrict__ tbf,
    const float* __restrict__ fwf, const float* __restrict__ fbf)
{
    int b = blockIdx.x;
    int c = threadIdx.x;
    float gt = 0.f, gf = 0.f;
    for (int oh = 0; oh < 56; oh++) {
        gt += g_part[0][(b * 56 + oh) * 128 + c];
        gf += g_part[1][(b * 56 + oh) * 128 + c];
    }
    const float inv = 1.0f / 3136.0f;
    gt *= inv; gf *= inv;
    float p0 = gt * twf[2 * c],     p1 = gt * twf[2 * c + 1];
    float p2 = gf * fwf[2 * c],     p3 = gf * fwf[2 * c + 1];
    #pragma unroll
    for (int off = 16; off; off >>= 1) {
        p0 += __shfl_xor_sync(0xffffffffu, p0, off);
        p1 += __shfl_xor_sync(0xffffffffu, p1, off);
        p2 += __shfl_xor_sync(0xffffffffu, p2, off);
        p3 += __shfl_xor_sync(0xffffffffu, p3, off);
    }
    __shared__ float s[4][4];
    int wid = c >> 5, lane = c & 31;
    if (lane == 0) { s[0][wid] = p0; s[1][wid] = p1; s[2][wid] = p2; s[3][wid] = p3; }
    __syncthreads();
    if (c == 0) {
        g_log[b * 4 + 0] = s[0][0] + s[0][1] + s[0][2] + s[0][3] + tbf[0];
        g_log[b * 4 + 1] = s[1][0] + s[1][1] + s[1][2] + s[1][3] + tbf[1];
        g_log[b * 4 + 2] = s[2][0] + s[2][1] + s[2][2] + s[2][3] + fbf[0];
        g_log[b * 4 + 3] = s[3][0] + s[3][1] + s[3][2] + s[3][3] + fbf[1];
    }
}

// ---------------------------------------------------------------------------
// final2: confidence, blend, freq_usage. 1 block, 64 threads (b).
// ---------------------------------------------------------------------------
__global__ void final2_kernel(float* __restrict__ out, int out_size)
{
    int b = threadIdx.x;
    float tl0 = g_log[b * 4 + 0], tl1 = g_log[b * 4 + 1];
    float fl0 = g_log[b * 4 + 2], fl1 = g_log[b * 4 + 3];
    // softmax max-prob of 2-class logits: 1 / (1 + exp(-|l0 - l1|))
    float conf = 1.0f / (1.0f + expf(-fabsf(tl0 - tl1)));
    bool use2 = (conf <= 0.9f);
    out[2 * b]     = use2 ? 0.7f * tl0 + 0.3f * fl0 : tl0;
    out[2 * b + 1] = use2 ? 0.7f * tl1 + 0.3f * fl1 : tl1;
    int n = __syncthreads_count(use2 ? 1 : 0);   // deterministic count
    if (b == 0) {
        float freq = (float)n / 64.0f;
        for (int j = 128; j < out_size; j++) out[j] = freq;
    }
}

// ---------------------------------------------------------------------------
extern "C" void kernel_launch(void* const* d_in, const int* in_sizes, int n_in,
                              void* d_out, int out_size)
{
    const float* x    = (const float*)d_in[0];
    const float* t_w1 = (const float*)d_in[1];
    const float* t_b1 = (const float*)d_in[2];
    const float* t_w2 = (const float*)d_in[3];
    const float* t_b2 = (const float*)d_in[4];
    const float* t_wf = (const float*)d_in[5];
    const float* t_bf = (const float*)d_in[6];
    const float* f_w1 = (const float*)d_in[7];
    const float* f_b1 = (const float*)d_in[8];
    const float* f_w2 = (const float*)d_in[9];
    const float* f_b2 = (const float*)d_in[10];
    const float* f_wf = (const float*)d_in[11];
    const float* f_bf = (const float*)d_in[12];
    float* out = (float*)d_out;

    dim3 g1(112, 64), g2(56, 64);
    // expert t
    conv1_kernel<<<g1, 256>>>(x, t_w1, t_b1);
    conv2_kernel<<<g2, 256>>>(0, t_w2, t_b2);
    // expert f (reuses g_h1)
    conv1_kernel<<<g1, 256>>>(x, f_w1, f_b1);
    conv2_kernel<<<g2, 256>>>(1, f_w2, f_b2);
    // head
    final1_kernel<<<64, 128>>>(t_wf, t_bf, f_wf, f_bf);
    final2_kernel<<<1, 64>>>(out, out_size);
}

// round 2
// speedup vs baseline: 1.4462x; 1.4462x over previous
#include <cuda_runtime.h>
#include <math.h>

// ---------------------------------------------------------------------------
//   x  : [64, 3, 224, 224] f32
//   w1 : [64, 3, 3, 3]   b1: [64]
//   w2 : [128, 64, 3, 3] b2: [128]
//   wf : [128, 2]        bf: [2]
// conv 3x3 stride2 SAME (pad_hi = 1)
//   h1 = relu(conv1(x))  : [B,64,112,112]
//   pooled conv2+relu    : -> g [B,128] (h2 never materialized)
//   logits = g@wf + bf
// blend by softmax confidence of expert t
// ---------------------------------------------------------------------------

__device__ float g_h1[2][64u * 64u * 112u * 112u];   // 411 MB scratch
__device__ float g_w2t[2][64 * 9 * 128];             // transposed conv2 weights [ic][k][oc]
__device__ float g_part[2][64 * 56 * 128];           // per-(b,oh) pooled partials
__device__ float g_log[64 * 4];

// ---------------------------------------------------------------------------
// one-time-per-replay transpose of conv2 weights: [oc][ic][k] -> [ic][k][oc]
// ---------------------------------------------------------------------------
__global__ void w2t_kernel(const float* __restrict__ tw2, const float* __restrict__ fw2)
{
    int idx = blockIdx.x * 256 + threadIdx.x;           // 2*64*9*128 = 147456
    if (idx >= 2 * 73728) return;
    int e   = idx / 73728;
    int rem = idx - e * 73728;
    int ic  = rem / 1152;
    int k   = (rem % 1152) / 128;
    int oc  = rem & 127;
    const float* w = e ? fw2 : tw2;
    g_w2t[e][rem] = w[oc * 576 + ic * 9 + k];
}

// ---------------------------------------------------------------------------
// conv1: x -> relu -> h1.   grid(112,64,2), 256 thr
// thread: 4 oc x 7 consecutive ow.  owg=tid&15 (ow0=7*owg), ocg=tid>>4 (oc0=4*ocg)
// ---------------------------------------------------------------------------
__global__ __launch_bounds__(256) void conv1_kernel(
    const float* __restrict__ x,
    const float* __restrict__ tw, const float* __restrict__ tb,
    const float* __restrict__ fw, const float* __restrict__ fb)
{
    int oh = blockIdx.x;
    int b  = blockIdx.y;
    int e  = blockIdx.z;
    const float* w    = e ? fw : tw;
    const float* bias = e ? fb : tb;

    __shared__ float s_in[3][3][228];   // [ic][r][col], cols >=224 are zero pad
    __shared__ float s_w[27][64];       // [ic*9 + r*3 + t][oc]
    __shared__ float s_b[64];
    int tid = threadIdx.x;

    // stage weights (tiny, uncoalesced OK)
    for (int i = tid; i < 27 * 64; i += 256) {
        int oc = i & 63, j = i >> 6;
        s_w[j][oc] = w[oc * 27 + j];
    }
    if (tid < 64) s_b[tid] = bias[tid];

    // stage input rows 2*oh .. 2*oh+2, vectorized
    for (int i = tid; i < 3 * 3 * 57; i += 256) {     // 57 float4 per 228-col row
        int c4  = i % 57;
        int t   = i / 57;
        int r   = t % 3;
        int ic  = t / 3;
        int ih  = 2 * oh + r;
        float4 v = make_float4(0.f, 0.f, 0.f, 0.f);
        if (ih < 224 && c4 < 56)
            v = *(const float4*)&x[(((size_t)b * 3 + ic) * 224 + ih) * 224 + 4 * c4];
        *(float4*)&s_in[ic][r][4 * c4] = v;
    }
    __syncthreads();

    int owg = tid & 15;
    int oc0 = (tid >> 4) * 4;
    int cb  = 14 * owg;

    float acc[4][7];
    #pragma unroll
    for (int u = 0; u < 4; u++) {
        float bv = s_b[oc0 + u];
        #pragma unroll
        for (int p = 0; p < 7; p++) acc[u][p] = bv;
    }

    #pragma unroll
    for (int ic = 0; ic < 3; ic++) {
        #pragma unroll
        for (int r = 0; r < 3; r++) {
            float4 w0 = *(float4*)&s_w[ic * 9 + r * 3 + 0][oc0];
            float4 w1 = *(float4*)&s_w[ic * 9 + r * 3 + 1][oc0];
            float4 w2 = *(float4*)&s_w[ic * 9 + r * 3 + 2][oc0];
            float2 c[8];
            #pragma unroll
            for (int q = 0; q < 8; q++)
                c[q] = *(float2*)&s_in[ic][r][cb + 2 * q];
            #pragma unroll
            for (int p = 0; p < 7; p++) {
                float i0 = c[p].x, i1 = c[p].y, i2 = c[p + 1].x;
                acc[0][p] += w0.x * i0 + w1.x * i1 + w2.x * i2;
                acc[1][p] += w0.y * i0 + w1.y * i1 + w2.y * i2;
                acc[2][p] += w0.z * i0 + w1.z * i1 + w2.z * i2;
                acc[3][p] += w0.w * i0 + w1.w * i1 + w2.w * i2;
            }
        }
    }

    #pragma unroll
    for (int u = 0; u < 4; u++) {
        float* op = &g_h1[e][(((size_t)b * 64 + oc0 + u) * 112 + oh) * 112 + 7 * owg];
        #pragma unroll
        for (int p = 0; p < 7; p++) {
            float v = acc[u][p];
            op[p] = v > 0.f ? v : 0.f;
        }
    }
}

// ---------------------------------------------------------------------------
// conv2 fused bias+relu+pool.  grid(56,64,2), 256 thr
// thread: 4 oc x 7 consecutive ow.  owg=tid&7 (ow0=7*owg), ocg=tid>>3 (oc0=4*ocg)
// ---------------------------------------------------------------------------
__global__ __launch_bounds__(256) void conv2_kernel(
    const float* __restrict__ tb, const float* __restrict__ fb)
{
    int oh = blockIdx.x;
    int b  = blockIdx.y;
    int e  = blockIdx.z;

    __shared__ float s_in[8][3][116];   // cols >=112 zero pad; stride 116 (16B-aligned rows)
    __shared__ float s_w[72][128];      // [icl*9 + k][oc]
    __shared__ float s_b[128];
    int tid = threadIdx.x;
    if (tid < 128) s_b[tid] = (e ? fb : tb)[tid];

    int owg = tid & 7;
    int oc0 = (tid >> 3) * 4;
    int cb  = 14 * owg;

    float acc[4][7];
    #pragma unroll
    for (int u = 0; u < 4; u++)
        #pragma unroll
        for (int p = 0; p < 7; p++) acc[u][p] = 0.f;

    const float* h1b = &g_h1[e][((size_t)b * 64) * 112 * 112];

    for (int ic0 = 0; ic0 < 64; ic0 += 8) {
        __syncthreads();
        // stage weights: coalesced gmem float4, conflict-free smem
        {
            const float* wt = &g_w2t[e][ic0 * 9 * 128];
            for (int i = tid; i < 72 * 32; i += 256) {
                int oc4 = i & 31, jj = i >> 5;
                *(float4*)&s_w[jj][4 * oc4] = *(const float4*)&wt[jj * 128 + 4 * oc4];
            }
        }
        // stage input: 8 ic x 3 rows x 29 float4
        for (int i = tid; i < 8 * 3 * 29; i += 256) {
            int c4  = i % 29;
            int t   = i / 29;
            int r   = t % 3;
            int icl = t / 3;
            int ih  = 2 * oh + r;
            float4 v = make_float4(0.f, 0.f, 0.f, 0.f);
            if (ih < 112 && c4 < 28)
                v = *(const float4*)&h1b[(((size_t)(ic0 + icl)) * 112 + ih) * 112 + 4 * c4];
            *(float4*)&s_in[icl][r][4 * c4] = v;
        }
        __syncthreads();

        #pragma unroll 2
        for (int icl = 0; icl < 8; icl++) {
            #pragma unroll
            for (int r = 0; r < 3; r++) {
                float4 w0 = *(float4*)&s_w[icl * 9 + r * 3 + 0][oc0];
                float4 w1 = *(float4*)&s_w[icl * 9 + r * 3 + 1][oc0];
                float4 w2 = *(float4*)&s_w[icl * 9 + r * 3 + 2][oc0];
                float2 c[8];
                #pragma unroll
                for (int q = 0; q < 8; q++)
                    c[q] = *(float2*)&s_in[icl][r][cb + 2 * q];
                #pragma unroll
                for (int p = 0; p < 7; p++) {
                    float i0 = c[p].x, i1 = c[p].y, i2 = c[p + 1].x;
                    acc[0][p] += w0.x * i0 + w1.x * i1 + w2.x * i2;
                    acc[1][p] += w0.y * i0 + w1.y * i1 + w2.y * i2;
                    acc[2][p] += w0.z * i0 + w1.z * i1 + w2.z * i2;
                    acc[3][p] += w0.w * i0 + w1.w * i1 + w2.w * i2;
                }
            }
        }
    }

    // bias + relu + pool 7 pixels, then reduce across the 8 ow-groups (lanes)
    #pragma unroll
    for (int u = 0; u < 4; u++) {
        float bv = s_b[oc0 + u];
        float s = 0.f;
        #pragma unroll
        for (int p = 0; p < 7; p++) {
            float v = acc[u][p] + bv;
            s += v > 0.f ? v : 0.f;
        }
        #pragma unroll
        for (int off = 4; off; off >>= 1)
            s += __shfl_down_sync(0xffffffffu, s, off);
        if (owg == 0)
            g_part[e][((b * 56 + oh) * 128) + oc0 + u] = s;   // deterministic
    }
}

// ---------------------------------------------------------------------------
// final1: finish GAP + FC.  grid 64 (b), 128 thr (c)
// ---------------------------------------------------------------------------
__global__ __launch_bounds__(128) void final1_kernel(
    const float* __restrict__ twf, const float* __restrict__ tbf,
    const float* __restrict__ fwf, const float* __restrict__ fbf)
{
    int b = blockIdx.x;
    int c = threadIdx.x;
    float gt = 0.f, gf = 0.f;
    for (int oh = 0; oh < 56; oh++) {
        gt += g_part[0][(b * 56 + oh) * 128 + c];
        gf += g_part[1][(b * 56 + oh) * 128 + c];
    }
    const float inv = 1.0f / 3136.0f;
    gt *= inv; gf *= inv;
    float p0 = gt * twf[2 * c], p1 = gt * twf[2 * c + 1];
    float p2 = gf * fwf[2 * c], p3 = gf * fwf[2 * c + 1];
    #pragma unroll
    for (int off = 16; off; off >>= 1) {
        p0 += __shfl_xor_sync(0xffffffffu, p0, off);
        p1 += __shfl_xor_sync(0xffffffffu, p1, off);
        p2 += __shfl_xor_sync(0xffffffffu, p2, off);
        p3 += __shfl_xor_sync(0xffffffffu, p3, off);
    }
    __shared__ float s[4][4];
    int wid = c >> 5, lane = c & 31;
    if (lane == 0) { s[0][wid] = p0; s[1][wid] = p1; s[2][wid] = p2; s[3][wid] = p3; }
    __syncthreads();
    if (c == 0) {
        g_log[b * 4 + 0] = s[0][0] + s[0][1] + s[0][2] + s[0][3] + tbf[0];
        g_log[b * 4 + 1] = s[1][0] + s[1][1] + s[1][2] + s[1][3] + tbf[1];
        g_log[b * 4 + 2] = s[2][0] + s[2][1] + s[2][2] + s[2][3] + fbf[0];
        g_log[b * 4 + 3] = s[3][0] + s[3][1] + s[3][2] + s[3][3] + fbf[1];
    }
}

// ---------------------------------------------------------------------------
__global__ void final2_kernel(float* __restrict__ out, int out_size)
{
    int b = threadIdx.x;
    float tl0 = g_log[b * 4 + 0], tl1 = g_log[b * 4 + 1];
    float fl0 = g_log[b * 4 + 2], fl1 = g_log[b * 4 + 3];
    float conf = 1.0f / (1.0f + expf(-fabsf(tl0 - tl1)));
    bool use2 = (conf <= 0.9f);
    out[2 * b]     = use2 ? 0.7f * tl0 + 0.3f * fl0 : tl0;
    out[2 * b + 1] = use2 ? 0.7f * tl1 + 0.3f * fl1 : tl1;
    int n = __syncthreads_count(use2 ? 1 : 0);
    if (b == 0) {
        float freq = (float)n / 64.0f;
        for (int j = 128; j < out_size; j++) out[j] = freq;
    }
}

// ---------------------------------------------------------------------------
extern "C" void kernel_launch(void* const* d_in, const int* in_sizes, int n_in,
                              void* d_out, int out_size)
{
    const float* x    = (const float*)d_in[0];
    const float* t_w1 = (const float*)d_in[1];
    const float* t_b1 = (const float*)d_in[2];
    const float* t_w2 = (const float*)d_in[3];
    const float* t_b2 = (const float*)d_in[4];
    const float* t_wf = (const float*)d_in[5];
    const float* t_bf = (const float*)d_in[6];
    const float* f_w1 = (const float*)d_in[7];
    const float* f_b1 = (const float*)d_in[8];
    const float* f_w2 = (const float*)d_in[9];
    const float* f_b2 = (const float*)d_in[10];
    const float* f_wf = (const float*)d_in[11];
    const float* f_bf = (const float*)d_in[12];
    float* out = (float*)d_out;

    w2t_kernel<<<(2 * 73728 + 255) / 256, 256>>>(t_w2, f_w2);
    conv1_kernel<<<dim3(112, 64, 2), 256>>>(x, t_w1, t_b1, f_w1, f_b1);
    conv2_kernel<<<dim3(56, 64, 2), 256>>>(t_b2, f_b2);
    final1_kernel<<<64, 128>>>(t_wf, t_bf, f_wf, f_bf);
    final2_kernel<<<1, 64>>>(out, out_size);
}